// round 8
// baseline (speedup 1.0000x reference)
#include <cuda_runtime.h>
#include <cstdint>

// Problem constants
#define BB 2
#define SS 2048
#define DD 1024
#define HH 16
#define DK 64
#define MROWS (BB * SS)   // 4096

// Scratch (static device globals — allocation-guard safe)
__device__ float g_q[MROWS * DD];
__device__ float g_k[MROWS * DD];
__device__ float g_v[MROWS * DD];
__device__ float g_o[MROWS * DD];
__device__ uint32_t g_qi[MROWS * DD];    // tf32 pre-converted inputs
__device__ uint32_t g_ki[MROWS * DD];
__device__ uint32_t g_vi[MROWS * DD];
__device__ uint32_t g_wt[4 * DD * DD];   // tf32 pre-converted weights

// ---------------------------------------------------------------------------
// Helpers
// ---------------------------------------------------------------------------
static __device__ __forceinline__ uint32_t f2tf32(float x) {
    uint32_t u;
    asm("cvt.rna.tf32.f32 %0, %1;" : "=r"(u) : "f"(x));
    return u;
}

static __device__ __forceinline__ uint32_t cvta_smem(const void* p) {
    uint32_t a;
    asm("{ .reg .u64 t; cvta.to.shared.u64 t, %1; cvt.u32.u64 %0, t; }"
        : "=r"(a) : "l"(p));
    return a;
}

static __device__ __forceinline__ void mma_tf32(float c[4], const uint32_t a[4],
                                                uint32_t b0, uint32_t b1) {
    asm volatile(
        "mma.sync.aligned.m16n8k8.row.col.f32.tf32.tf32.f32 "
        "{%0,%1,%2,%3}, {%4,%5,%6,%7}, {%8,%9}, {%0,%1,%2,%3};"
        : "+f"(c[0]), "+f"(c[1]), "+f"(c[2]), "+f"(c[3])
        : "r"(a[0]), "r"(a[1]), "r"(a[2]), "r"(a[3]), "r"(b0), "r"(b1));
}

static __device__ __forceinline__ void ldsm_x4(uint32_t r[4], uint32_t addr) {
    asm volatile("ldmatrix.sync.aligned.m8n8.x4.shared.b16 {%0,%1,%2,%3}, [%4];"
        : "=r"(r[0]), "=r"(r[1]), "=r"(r[2]), "=r"(r[3]) : "r"(addr));
}

static __device__ __forceinline__ void cp16(uint32_t dst, const void* src) {
    asm volatile("cp.async.cg.shared.global [%0], [%1], 16;"
                 :: "r"(dst), "l"(src) : "memory");
}
#define CP_COMMIT() asm volatile("cp.async.commit_group;" ::: "memory")
#define CP_WAIT(n)  asm volatile("cp.async.wait_group %0;" :: "n"(n) : "memory")

// ---------------------------------------------------------------------------
// Prepass: fp32 -> tf32(rna) bits for 3 inputs (4M elems) + 4 weights (1M elems)
// grid (4096, 7) x 256 threads; weights use only the first 1024 blocks.
// ---------------------------------------------------------------------------
__global__ __launch_bounds__(256) void cvt7_kernel(
    const float* __restrict__ iq, const float* __restrict__ ik, const float* __restrict__ iv,
    const float* __restrict__ wq, const float* __restrict__ wk,
    const float* __restrict__ wv, const float* __restrict__ wo,
    uint32_t* __restrict__ dq, uint32_t* __restrict__ dk, uint32_t* __restrict__ dv,
    uint32_t* __restrict__ dw)
{
    const int y = blockIdx.y;
    const float* src;
    uint32_t* dst;
    if (y < 3) {
        src = (y == 0) ? iq : (y == 1) ? ik : iv;
        dst = (y == 0) ? dq : (y == 1) ? dk : dv;
    } else {
        if (blockIdx.x >= 1024) return;
        src = (y == 3) ? wq : (y == 4) ? wk : (y == 5) ? wv : wo;
        dst = dw + (size_t)(y - 3) * DD * DD;
    }
    const int idx = blockIdx.x * 256 + threadIdx.x;   // float4 index
    float4 v = *(const float4*)(src + (size_t)idx * 4);
    uint4 o = make_uint4(f2tf32(v.x), f2tf32(v.y), f2tf32(v.z), f2tf32(v.w));
    *(uint4*)(dst + (size_t)idx * 4) = o;
}

// ---------------------------------------------------------------------------
// Pure-cp.async tf32 GEMM: C[z] = A[z] @ W[z]^T + bias[z].
// CTA tile 128x128, BK=16, 128 threads (4 warps of 64x64), 4-stage pipeline.
// All operands pre-converted tf32 bits. Swizzle: 64B rows, col c^((row>>1)&3).
// ---------------------------------------------------------------------------
#define STG 16384                     // bytes per stage (A 8KB + B 8KB)
#define GEMM_SMEM (4 * STG)           // 65536 B

__global__ __launch_bounds__(128, 2) void gemm_cp2_kernel(
    const uint32_t* __restrict__ A0, const uint32_t* __restrict__ A1,
    const uint32_t* __restrict__ A2, const uint32_t* __restrict__ Wbase,
    const float* __restrict__ b0p, const float* __restrict__ b1p, const float* __restrict__ b2p,
    float* __restrict__ C0, float* __restrict__ C1, float* __restrict__ C2,
    int doRound)
{
    extern __shared__ uint32_t smem[];

    const int z = blockIdx.z;
    const uint32_t* A = (z == 0) ? A0 : (z == 1) ? A1 : A2;
    const uint32_t* W = Wbase + (size_t)z * DD * DD;
    const float* bias = (z == 0) ? b0p : (z == 1) ? b1p : b2p;
    float* C = (z == 0) ? C0 : (z == 1) ? C1 : C2;

    const int tid = threadIdx.x;
    const int lane = tid & 31;
    const int wid = tid >> 5;        // 0..3
    const int wm = wid & 1;          // 64-row slice
    const int wn = wid >> 1;         // 64-col slice
    const int l4 = lane >> 2;
    const int lm = lane & 3;
    const int rowBase = blockIdx.y * 128;
    const int colBase = blockIdx.x * 128;

    const uint32_t smb = cvta_smem(smem);

    // ldmatrix fragment addressing (swizzled 64B rows)
    uint32_t aRowOff[4], bRowOff[4], swA[4], swB[4];
#pragma unroll
    for (int mt = 0; mt < 4; mt++) {
        int r = wm * 64 + mt * 16 + (lane & 15);
        aRowOff[mt] = r * 64;
        swA[mt] = (r >> 1) & 3;
    }
#pragma unroll
    for (int t = 0; t < 4; t++) {
        int r = wn * 64 + t * 16 + (lane & 7) + 8 * ((lane >> 4) & 1);
        bRowOff[t] = r * 64;
        swB[t] = (r >> 1) & 3;
    }
    const uint32_t c0a = lane >> 4;
    const uint32_t c0b = (lane >> 3) & 1;

    float acc[4][8][4];
#pragma unroll
    for (int mt = 0; mt < 4; mt++)
#pragma unroll
        for (int nt = 0; nt < 8; nt++)
#pragma unroll
            for (int r = 0; r < 4; r++) acc[mt][nt][r] = 0.0f;

    // per-chunk cp.async: thread -> row tid (A rows 0..127, B rows 0..127), 4x16B
    const uint32_t swT = (tid >> 1) & 3;
    const uint32_t* aSrc = A + (size_t)(rowBase + tid) * DD;
    const uint32_t* bSrc = W + (size_t)(colBase + tid) * DD;
    auto issueAB = [&](int j) {
        const uint32_t st = smb + (j & 3) * STG + tid * 64;
#pragma unroll
        for (int c = 0; c < 4; c++) {
            cp16(st + ((c ^ swT) << 4), aSrc + j * 16 + c * 4);
            cp16(st + 8192 + ((c ^ swT) << 4), bSrc + j * 16 + c * 4);
        }
        CP_COMMIT();
    };

    const int nChunks = DD / 16;   // 64
    issueAB(0); issueAB(1); issueAB(2);

    for (int ic = 0; ic < nChunks; ic++) {
        if (ic <= nChunks - 3)      { CP_WAIT(2); }
        else if (ic == nChunks - 2) { CP_WAIT(1); }
        else                        { CP_WAIT(0); }
        __syncthreads();
        // safe to refill stage (ic+3)&3: its last readers (chunk ic-1) are
        // behind the barrier above
        if (ic + 3 < nChunks) issueAB(ic + 3);

        const uint32_t aBase = smb + (ic & 3) * STG;
        const uint32_t bBase = aBase + 8192;
#pragma unroll
        for (int ks = 0; ks < 2; ks++) {
            const uint32_t ca = c0a + ks * 2;
            const uint32_t cb = c0b + ks * 2;
            uint32_t af[4][4];
#pragma unroll
            for (int mt = 0; mt < 4; mt++)
                ldsm_x4(af[mt], aBase + aRowOff[mt] + ((ca ^ swA[mt]) << 4));
#pragma unroll
            for (int t = 0; t < 4; t++) {
                uint32_t bb[4];
                ldsm_x4(bb, bBase + bRowOff[t] + ((cb ^ swB[t]) << 4));
#pragma unroll
                for (int mt = 0; mt < 4; mt++) {
                    mma_tf32(acc[mt][2 * t],     af[mt], bb[0], bb[1]);
                    mma_tf32(acc[mt][2 * t + 1], af[mt], bb[2], bb[3]);
                }
            }
        }
    }

    // epilogue: bias + (optional tf32 round) + store
#pragma unroll
    for (int nt = 0; nt < 8; nt++) {
        int c = colBase + wn * 64 + nt * 8 + 2 * lm;
        float2 bv = *(const float2*)(bias + c);
#pragma unroll
        for (int mt = 0; mt < 4; mt++) {
            int r = rowBase + wm * 64 + mt * 16 + l4;
            float2 o0 = make_float2(acc[mt][nt][0] + bv.x, acc[mt][nt][1] + bv.y);
            float2 o1 = make_float2(acc[mt][nt][2] + bv.x, acc[mt][nt][3] + bv.y);
            if (doRound) {
                o0.x = __uint_as_float(f2tf32(o0.x)); o0.y = __uint_as_float(f2tf32(o0.y));
                o1.x = __uint_as_float(f2tf32(o1.x)); o1.y = __uint_as_float(f2tf32(o1.y));
            }
            *(float2*)(C + (size_t)r * DD + c) = o0;
            *(float2*)(C + (size_t)(r + 8) * DD + c) = o1;
        }
    }
}

// ---------------------------------------------------------------------------
// Flash attention (causal), tf32 mma.sync, ldmatrix frags.
// Inputs pre-rounded to tf32 -> bit-copy instead of cvt.
// ---------------------------------------------------------------------------
#define FS 68

__global__ __launch_bounds__(256) void flash_mma_kernel(
    const float* __restrict__ Qg, const float* __restrict__ Kg,
    const float* __restrict__ Vg, float* __restrict__ Og)
{
    extern __shared__ uint32_t sm[];
    uint32_t* Ps = sm + 4 * 64 * FS;

    const int tid = threadIdx.x;
    const int lane = tid & 31;
    const int wid = tid >> 5;
    const int l4 = lane >> 2;
    const int lm = lane & 3;

    const int qt = (gridDim.x - 1) - blockIdx.x;   // heavy tiles first
    const int h  = blockIdx.y;
    const int b  = blockIdx.z;
    const int q0 = qt * 128;

    const size_t base = (size_t)b * SS * DD + (size_t)h * DK;

    const int gr0 = q0 + wid * 16 + l4;
    const int prow = wid * 16 + l4;

    const uint32_t smb = cvta_smem(sm);
    const uint32_t psb = smb + 4 * 64 * FS * 4;

    uint32_t kvOff[4];
#pragma unroll
    for (int t = 0; t < 4; t++)
        kvOff[t] = ((t * 16 + (lane & 7) + 8 * ((lane >> 4) & 1)) * FS
                    + 4 * ((lane >> 3) & 1)) * 4;
    const uint32_t pOff = ((wid * 16 + (lane & 15)) * FS + ((lane >> 4) << 2)) * 4;

    // Q fragments (pre-rounded tf32 bits)
    uint32_t qf[8][4];
#pragma unroll
    for (int ks = 0; ks < 8; ks++) {
        const float* q0p = Qg + base + (size_t)gr0 * DD;
        const float* q1p = Qg + base + (size_t)(gr0 + 8) * DD;
        qf[ks][0] = __float_as_uint(q0p[ks * 8 + lm]);
        qf[ks][1] = __float_as_uint(q1p[ks * 8 + lm]);
        qf[ks][2] = __float_as_uint(q0p[ks * 8 + lm + 4]);
        qf[ks][3] = __float_as_uint(q1p[ks * 8 + lm + 4]);
    }

    float oacc[8][4];
#pragma unroll
    for (int dt = 0; dt < 8; dt++)
#pragma unroll
        for (int r = 0; r < 4; r++) oacc[dt][r] = 0.0f;
    float m0 = -1e30f, m1 = -1e30f, l0 = 0.0f, l1 = 0.0f;

    float4 kr[4];
    float vr[16];
    auto load_kv = [&](int kt) {
        const int k0 = kt * 64;
#pragma unroll
        for (int i = 0; i < 4; i++) {
            int fi = tid + 256 * i;
            int row = fi >> 4;
            int c4 = (fi & 15) * 4;
            kr[i] = *(const float4*)(Kg + base + (size_t)(k0 + row) * DD + c4);
        }
#pragma unroll
        for (int i = 0; i < 16; i++) {
            int fi = tid + 256 * i;
            int row = fi >> 6;
            int d = fi & 63;
            vr[i] = Vg[base + (size_t)(k0 + row) * DD + d];
        }
    };
    auto store_kv = [&](int buf) {
        uint32_t* Ks = sm + buf * 64 * FS;
        uint32_t* Vt = sm + (2 + buf) * 64 * FS;
#pragma unroll
        for (int i = 0; i < 4; i++) {
            int fi = tid + 256 * i;
            int row = fi >> 4;
            int c4 = (fi & 15) * 4;
            uint32_t* dst = Ks + row * FS + c4;
            dst[0] = __float_as_uint(kr[i].x); dst[1] = __float_as_uint(kr[i].y);
            dst[2] = __float_as_uint(kr[i].z); dst[3] = __float_as_uint(kr[i].w);
        }
#pragma unroll
        for (int i = 0; i < 16; i++) {
            int fi = tid + 256 * i;
            int row = fi >> 6;
            int d = fi & 63;
            Vt[d * FS + row] = __float_as_uint(vr[i]);
        }
    };

    load_kv(0);
    store_kv(0);
    __syncthreads();

    const int nkt = 2 * qt + 2;
    for (int kt = 0; kt < nkt; kt++) {
        const int k0 = kt * 64;
        const int buf = kt & 1;
        const uint32_t ksBuf = smb + buf * 64 * FS * 4;
        const uint32_t vtBuf = smb + (2 + buf) * 64 * FS * 4;

        float sf[8][4];
#pragma unroll
        for (int nt = 0; nt < 8; nt++)
#pragma unroll
            for (int r = 0; r < 4; r++) sf[nt][r] = 0.0f;

#pragma unroll
        for (int ks = 0; ks < 8; ks++) {
            const uint32_t kbB = ks * 32;
#pragma unroll
            for (int t = 0; t < 4; t++) {
                uint32_t bb[4];
                ldsm_x4(bb, ksBuf + kvOff[t] + kbB);
                mma_tf32(sf[2 * t],     qf[ks], bb[0], bb[1]);
                mma_tf32(sf[2 * t + 1], qf[ks], bb[2], bb[3]);
            }
        }

        if (kt + 1 < nkt) load_kv(kt + 1);

        const float scale = 0.125f;
#pragma unroll
        for (int nt = 0; nt < 8; nt++)
#pragma unroll
            for (int r = 0; r < 4; r++) sf[nt][r] *= scale;

        if (k0 + 63 > q0 + wid * 16) {
#pragma unroll
            for (int nt = 0; nt < 8; nt++) {
                int c = k0 + nt * 8 + 2 * lm;
                if (c     > gr0)     sf[nt][0] = -1e30f;
                if (c + 1 > gr0)     sf[nt][1] = -1e30f;
                if (c     > gr0 + 8) sf[nt][2] = -1e30f;
                if (c + 1 > gr0 + 8) sf[nt][3] = -1e30f;
            }
        }

        float rm0 = -1e30f, rm1 = -1e30f;
#pragma unroll
        for (int nt = 0; nt < 8; nt++) {
            rm0 = fmaxf(rm0, fmaxf(sf[nt][0], sf[nt][1]));
            rm1 = fmaxf(rm1, fmaxf(sf[nt][2], sf[nt][3]));
        }
#pragma unroll
        for (int off = 1; off <= 2; off <<= 1) {
            rm0 = fmaxf(rm0, __shfl_xor_sync(0xffffffffu, rm0, off));
            rm1 = fmaxf(rm1, __shfl_xor_sync(0xffffffffu, rm1, off));
        }
        float nm0 = fmaxf(m0, rm0), nm1 = fmaxf(m1, rm1);
        float a0 = __expf(m0 - nm0), a1 = __expf(m1 - nm1);
        float rs0 = 0.0f, rs1 = 0.0f;
#pragma unroll
        for (int nt = 0; nt < 8; nt++) {
            sf[nt][0] = __expf(sf[nt][0] - nm0);
            sf[nt][1] = __expf(sf[nt][1] - nm0);
            sf[nt][2] = __expf(sf[nt][2] - nm1);
            sf[nt][3] = __expf(sf[nt][3] - nm1);
            rs0 += sf[nt][0] + sf[nt][1];
            rs1 += sf[nt][2] + sf[nt][3];
        }
#pragma unroll
        for (int off = 1; off <= 2; off <<= 1) {
            rs0 += __shfl_xor_sync(0xffffffffu, rs0, off);
            rs1 += __shfl_xor_sync(0xffffffffu, rs1, off);
        }
        l0 = l0 * a0 + rs0;  m0 = nm0;
        l1 = l1 * a1 + rs1;  m1 = nm1;
#pragma unroll
        for (int dt = 0; dt < 8; dt++) {
            oacc[dt][0] *= a0; oacc[dt][1] *= a0;
            oacc[dt][2] *= a1; oacc[dt][3] *= a1;
        }

#pragma unroll
        for (int nt = 0; nt < 8; nt++) {
            int c = nt * 8 + 2 * lm;
            uint32_t p0 = f2tf32(sf[nt][0]), p1 = f2tf32(sf[nt][1]);
            uint32_t p2 = f2tf32(sf[nt][2]), p3 = f2tf32(sf[nt][3]);
            *(uint2*)&Ps[prow * FS + c]       = make_uint2(p0, p1);
            *(uint2*)&Ps[(prow + 8) * FS + c] = make_uint2(p2, p3);
        }
        __syncwarp();

#pragma unroll
        for (int ks = 0; ks < 8; ks++) {
            const uint32_t kbB = ks * 32;
            uint32_t af[4];
            ldsm_x4(af, psb + pOff + kbB);
#pragma unroll
            for (int t = 0; t < 4; t++) {
                uint32_t bb[4];
                ldsm_x4(bb, vtBuf + kvOff[t] + kbB);
                mma_tf32(oacc[2 * t],     af, bb[0], bb[1]);
                mma_tf32(oacc[2 * t + 1], af, bb[2], bb[3]);
            }
        }

        if (kt + 1 < nkt) {
            store_kv(buf ^ 1);
            __syncthreads();
        }
    }

    // normalize + round to tf32 (consumed by tf32 output projection)
    float inv0 = 1.0f / l0, inv1 = 1.0f / l1;
#pragma unroll
    for (int dt = 0; dt < 8; dt++) {
        int d = dt * 8 + 2 * lm;
        float2 o0, o1;
        o0.x = __uint_as_float(f2tf32(oacc[dt][0] * inv0));
        o0.y = __uint_as_float(f2tf32(oacc[dt][1] * inv0));
        o1.x = __uint_as_float(f2tf32(oacc[dt][2] * inv1));
        o1.y = __uint_as_float(f2tf32(oacc[dt][3] * inv1));
        *(float2*)(Og + base + (size_t)gr0 * DD + d) = o0;
        *(float2*)(Og + base + (size_t)(gr0 + 8) * DD + d) = o1;
    }
}

// ---------------------------------------------------------------------------
// Launch
// ---------------------------------------------------------------------------
extern "C" void kernel_launch(void* const* d_in, const int* in_sizes, int n_in,
                              void* d_out, int out_size)
{
    const float* query = (const float*)d_in[0];
    const float* key   = (const float*)d_in[1];
    const float* value = (const float*)d_in[2];
    const float* wq = (const float*)d_in[3];
    const float* bq = (const float*)d_in[4];
    const float* wk = (const float*)d_in[5];
    const float* bk = (const float*)d_in[6];
    const float* wv = (const float*)d_in[7];
    const float* bv = (const float*)d_in[8];
    const float* wo = (const float*)d_in[9];
    const float* bo = (const float*)d_in[10];
    float* out = (float*)d_out;

    float *q_s, *k_s, *v_s, *o_s;
    uint32_t *qi, *ki, *vi, *wt;
    cudaGetSymbolAddress((void**)&q_s, g_q);
    cudaGetSymbolAddress((void**)&k_s, g_k);
    cudaGetSymbolAddress((void**)&v_s, g_v);
    cudaGetSymbolAddress((void**)&o_s, g_o);
    cudaGetSymbolAddress((void**)&qi, g_qi);
    cudaGetSymbolAddress((void**)&ki, g_ki);
    cudaGetSymbolAddress((void**)&vi, g_vi);
    cudaGetSymbolAddress((void**)&wt, g_wt);

    const int smem_attn = (4 * 64 + 128) * FS * sizeof(uint32_t);  // 104448 B
    cudaFuncSetAttribute(flash_mma_kernel,
                         cudaFuncAttributeMaxDynamicSharedMemorySize, smem_attn);
    cudaFuncSetAttribute(gemm_cp2_kernel,
                         cudaFuncAttributeMaxDynamicSharedMemorySize, GEMM_SMEM);

    // 1. pre-convert inputs + weights to tf32
    cvt7_kernel<<<dim3(4096, 7), 256>>>(query, key, value, wq, wk, wv, wo,
                                        qi, ki, vi, wt);

    // 2. fused q/k/v projections (outputs tf32-rounded)
    dim3 gproj3(DD / 128, MROWS / 128, 3);
    gemm_cp2_kernel<<<gproj3, 128, GEMM_SMEM>>>(qi, ki, vi, wt,
                                                bq, bk, bv, q_s, k_s, v_s, 1);

    // 3. flash attention (outputs tf32-rounded)
    dim3 gattn(SS / 128, HH, BB);
    flash_mma_kernel<<<gattn, 256, smem_attn>>>(q_s, k_s, v_s, o_s);

    // 4. output projection (full fp32 output); A = o_s (already tf32 bits)
    dim3 gproj1(DD / 128, MROWS / 128, 1);
    gemm_cp2_kernel<<<gproj1, 128, GEMM_SMEM>>>(
        (const uint32_t*)o_s, (const uint32_t*)o_s, (const uint32_t*)o_s,
        wt + 3ull * DD * DD, bo, bo, bo, out, out, out, 0);
}

// round 9
// speedup vs baseline: 1.2253x; 1.2253x over previous
#include <cuda_runtime.h>
#include <cstdint>

// Problem constants
#define BB 2
#define SS 2048
#define DD 1024
#define HH 16
#define DK 64
#define MROWS (BB * SS)   // 4096

// Scratch (static device globals — allocation-guard safe)
__device__ float g_q[MROWS * DD];
__device__ float g_k[MROWS * DD];
__device__ float g_v[MROWS * DD];
__device__ float g_o[MROWS * DD];

// ---------------------------------------------------------------------------
// Helpers
// ---------------------------------------------------------------------------
static __device__ __forceinline__ uint32_t f2tf32(float x) {
    uint32_t u;
    asm("cvt.rna.tf32.f32 %0, %1;" : "=r"(u) : "f"(x));
    return u;
}

static __device__ __forceinline__ uint32_t cvta_smem(const void* p) {
    uint32_t a;
    asm("{ .reg .u64 t; cvta.to.shared.u64 t, %1; cvt.u32.u64 %0, t; }"
        : "=r"(a) : "l"(p));
    return a;
}

static __device__ __forceinline__ void mma_tf32(float c[4], const uint32_t a[4],
                                                uint32_t b0, uint32_t b1) {
    asm volatile(
        "mma.sync.aligned.m16n8k8.row.col.f32.tf32.tf32.f32 "
        "{%0,%1,%2,%3}, {%4,%5,%6,%7}, {%8,%9}, {%0,%1,%2,%3};"
        : "+f"(c[0]), "+f"(c[1]), "+f"(c[2]), "+f"(c[3])
        : "r"(a[0]), "r"(a[1]), "r"(a[2]), "r"(a[3]), "r"(b0), "r"(b1));
}

static __device__ __forceinline__ void ldsm_x4(uint32_t r[4], uint32_t addr) {
    asm volatile("ldmatrix.sync.aligned.m8n8.x4.shared.b16 {%0,%1,%2,%3}, [%4];"
        : "=r"(r[0]), "=r"(r[1]), "=r"(r[2]), "=r"(r[3]) : "r"(addr));
}

// ---------------------------------------------------------------------------
// Fused tf32 mma.sync GEMM (R6 config — proven fastest):
// C[z] = A[z] @ W[z]^T + bias[z]. CTA tile 128x128, BK=16,
// 128 threads (4 warps of 64x64), reg-prefetch + STS double buffer.
// ---------------------------------------------------------------------------
#define BK 16
#define APAD 20
#define GBUF (128 * APAD)      // words per buffer

__global__ __launch_bounds__(128, 2) void gemm3_mma_kernel(
    const float* __restrict__ A0, const float* __restrict__ A1, const float* __restrict__ A2,
    const float* __restrict__ W0, const float* __restrict__ W1, const float* __restrict__ W2,
    const float* __restrict__ b0p, const float* __restrict__ b1p, const float* __restrict__ b2p,
    float* __restrict__ C0, float* __restrict__ C1, float* __restrict__ C2)
{
    __shared__ uint32_t As[2][GBUF];
    __shared__ uint32_t Bs[2][GBUF];

    const int z = blockIdx.z;
    const float* A = (z == 0) ? A0 : (z == 1) ? A1 : A2;
    const float* W = (z == 0) ? W0 : (z == 1) ? W1 : W2;
    const float* bias = (z == 0) ? b0p : (z == 1) ? b1p : b2p;
    float* C = (z == 0) ? C0 : (z == 1) ? C1 : C2;

    const int tid = threadIdx.x;
    const int lane = tid & 31;
    const int wid = tid >> 5;        // 0..3
    const int wm = wid & 1;          // 64-row slice
    const int wn = wid >> 1;         // 64-col slice
    const int l4 = lane >> 2;
    const int lm = lane & 3;
    const int rowBase = blockIdx.y * 128;
    const int colBase = blockIdx.x * 128;

    const uint32_t asb = cvta_smem(As);
    const uint32_t bsb = cvta_smem(Bs);

    uint32_t aOff[4], bOff[4];
#pragma unroll
    for (int mt = 0; mt < 4; mt++)
        aOff[mt] = ((wm * 64 + mt * 16 + (lane & 15)) * APAD + ((lane >> 4) << 2)) * 4;
#pragma unroll
    for (int t = 0; t < 4; t++)
        bOff[t] = ((wn * 64 + t * 16 + (lane & 7) + 8 * ((lane >> 4) & 1)) * APAD
                   + 4 * ((lane >> 3) & 1)) * 4;

    float acc[4][8][4];
#pragma unroll
    for (int mt = 0; mt < 4; mt++)
#pragma unroll
        for (int nt = 0; nt < 8; nt++)
#pragma unroll
            for (int r = 0; r < 4; r++) acc[mt][nt][r] = 0.0f;

    float4 ra[4], rb[4];
    auto loadg = [&](int ic) {
        const int kOff = ic * BK;
#pragma unroll
        for (int i = 0; i < 4; i++) {
            int fi = tid + 128 * i;
            int row = fi >> 2;
            int k4 = fi & 3;
            ra[i] = *(const float4*)(A + (size_t)(rowBase + row) * DD + kOff + k4 * 4);
            rb[i] = *(const float4*)(W + (size_t)(colBase + row) * DD + kOff + k4 * 4);
        }
    };

    loadg(0);
    const int nChunks = DD / BK;   // 64

    for (int ic = 0; ic < nChunks; ic++) {
        const int buf = ic & 1;
        const uint32_t bufB = buf * (GBUF * 4);
#pragma unroll
        for (int i = 0; i < 4; i++) {
            int fi = tid + 128 * i;
            int row = fi >> 2;
            int k4 = fi & 3;
            uint32_t* da = &As[buf][row * APAD + k4 * 4];
            da[0] = f2tf32(ra[i].x); da[1] = f2tf32(ra[i].y);
            da[2] = f2tf32(ra[i].z); da[3] = f2tf32(ra[i].w);
            uint32_t* db = &Bs[buf][row * APAD + k4 * 4];
            db[0] = f2tf32(rb[i].x); db[1] = f2tf32(rb[i].y);
            db[2] = f2tf32(rb[i].z); db[3] = f2tf32(rb[i].w);
        }
        __syncthreads();

        if (ic + 1 < nChunks) loadg(ic + 1);

#pragma unroll
        for (int ks = 0; ks < 2; ks++) {
            const uint32_t kbB = ks * 32;   // 8 words
            uint32_t af[4][4];
#pragma unroll
            for (int mt = 0; mt < 4; mt++)
                ldsm_x4(af[mt], asb + bufB + aOff[mt] + kbB);
#pragma unroll
            for (int t = 0; t < 4; t++) {
                uint32_t bb[4];
                ldsm_x4(bb, bsb + bufB + bOff[t] + kbB);
#pragma unroll
                for (int mt = 0; mt < 4; mt++) {
                    mma_tf32(acc[mt][2 * t],     af[mt], bb[0], bb[1]);
                    mma_tf32(acc[mt][2 * t + 1], af[mt], bb[2], bb[3]);
                }
            }
        }
        // no trailing sync: double-buffered smem
    }

    // epilogue: bias + store
#pragma unroll
    for (int nt = 0; nt < 8; nt++) {
        int c = colBase + wn * 64 + nt * 8 + 2 * lm;
        float2 bv = *(const float2*)(bias + c);
#pragma unroll
        for (int mt = 0; mt < 4; mt++) {
            int r = rowBase + wm * 64 + mt * 16 + l4;
            float2 o0 = make_float2(acc[mt][nt][0] + bv.x, acc[mt][nt][1] + bv.y);
            float2 o1 = make_float2(acc[mt][nt][2] + bv.x, acc[mt][nt][3] + bv.y);
            *(float2*)(C + (size_t)r * DD + c) = o0;
            *(float2*)(C + (size_t)(r + 8) * DD + c) = o1;
        }
    }
}

// ---------------------------------------------------------------------------
// Flash attention (causal), tf32 mma.sync, ldmatrix frags.
// NEW: 128 threads (4 warps), 64 q-rows per CTA -> 2 CTAs/SM (reg-fit),
// double-buffered K/V smem, single sync per tile, heavy-tiles-first order.
// ---------------------------------------------------------------------------
#define FS 68
#define FLASH_SMEM ((4 * 64 + 64) * FS * 4)   // 87040 B

__global__ __launch_bounds__(128, 2) void flash_mma_kernel(
    const float* __restrict__ Qg, const float* __restrict__ Kg,
    const float* __restrict__ Vg, float* __restrict__ Og)
{
    extern __shared__ uint32_t sm[];
    uint32_t* Ps = sm + 4 * 64 * FS;   // [64][FS]

    const int tid = threadIdx.x;
    const int lane = tid & 31;
    const int wid = tid >> 5;          // 0..3
    const int l4 = lane >> 2;
    const int lm = lane & 3;

    const int qt = (gridDim.x - 1) - blockIdx.x;   // heavy tiles first
    const int h  = blockIdx.y;
    const int b  = blockIdx.z;
    const int q0 = qt * 64;

    const size_t base = (size_t)b * SS * DD + (size_t)h * DK;

    const int gr0 = q0 + wid * 16 + l4;
    const int prow = wid * 16 + l4;

    const uint32_t smb = cvta_smem(sm);
    const uint32_t psb = smb + 4 * 64 * FS * 4;

    uint32_t kvOff[4];
#pragma unroll
    for (int t = 0; t < 4; t++)
        kvOff[t] = ((t * 16 + (lane & 7) + 8 * ((lane >> 4) & 1)) * FS
                    + 4 * ((lane >> 3) & 1)) * 4;
    const uint32_t pOff = ((wid * 16 + (lane & 15)) * FS + ((lane >> 4) << 2)) * 4;

    // Q fragments in registers (16 rows x 64 k per warp)
    uint32_t qf[8][4];
#pragma unroll
    for (int ks = 0; ks < 8; ks++) {
        const float* q0p = Qg + base + (size_t)gr0 * DD;
        const float* q1p = Qg + base + (size_t)(gr0 + 8) * DD;
        qf[ks][0] = f2tf32(q0p[ks * 8 + lm]);
        qf[ks][1] = f2tf32(q1p[ks * 8 + lm]);
        qf[ks][2] = f2tf32(q0p[ks * 8 + lm + 4]);
        qf[ks][3] = f2tf32(q1p[ks * 8 + lm + 4]);
    }

    float oacc[8][4];
#pragma unroll
    for (int dt = 0; dt < 8; dt++)
#pragma unroll
        for (int r = 0; r < 4; r++) oacc[dt][r] = 0.0f;
    float m0 = -1e30f, m1 = -1e30f, l0 = 0.0f, l1 = 0.0f;

    // K/V tile register prefetch (128 threads: 8 float4 K, 32 scalar V)
    float4 kr[8];
    float vr[32];
    auto load_kv = [&](int kt) {
        const int k0 = kt * 64;
#pragma unroll
        for (int i = 0; i < 8; i++) {
            int fi = tid + 128 * i;
            int row = fi >> 4;
            int c4 = (fi & 15) * 4;
            kr[i] = *(const float4*)(Kg + base + (size_t)(k0 + row) * DD + c4);
        }
#pragma unroll
        for (int i = 0; i < 32; i++) {
            int fi = tid + 128 * i;
            int row = fi >> 6;
            int d = fi & 63;
            vr[i] = Vg[base + (size_t)(k0 + row) * DD + d];
        }
    };
    auto store_kv = [&](int buf) {
        uint32_t* Ks = sm + buf * 64 * FS;
        uint32_t* Vt = sm + (2 + buf) * 64 * FS;
#pragma unroll
        for (int i = 0; i < 8; i++) {
            int fi = tid + 128 * i;
            int row = fi >> 4;
            int c4 = (fi & 15) * 4;
            uint32_t* dst = Ks + row * FS + c4;
            dst[0] = f2tf32(kr[i].x); dst[1] = f2tf32(kr[i].y);
            dst[2] = f2tf32(kr[i].z); dst[3] = f2tf32(kr[i].w);
        }
#pragma unroll
        for (int i = 0; i < 32; i++) {
            int fi = tid + 128 * i;
            int row = fi >> 6;
            int d = fi & 63;
            Vt[d * FS + row] = f2tf32(vr[i]);
        }
    };

    load_kv(0);
    store_kv(0);
    __syncthreads();

    const int nkt = qt + 1;
    for (int kt = 0; kt < nkt; kt++) {
        const int k0 = kt * 64;
        const int buf = kt & 1;
        const uint32_t ksBuf = smb + buf * 64 * FS * 4;
        const uint32_t vtBuf = smb + (2 + buf) * 64 * FS * 4;

        // S = Q @ K^T
        float sf[8][4];
#pragma unroll
        for (int nt = 0; nt < 8; nt++)
#pragma unroll
            for (int r = 0; r < 4; r++) sf[nt][r] = 0.0f;

#pragma unroll
        for (int ks = 0; ks < 8; ks++) {
            const uint32_t kbB = ks * 32;
#pragma unroll
            for (int t = 0; t < 4; t++) {
                uint32_t bb[4];
                ldsm_x4(bb, ksBuf + kvOff[t] + kbB);
                mma_tf32(sf[2 * t],     qf[ks], bb[0], bb[1]);
                mma_tf32(sf[2 * t + 1], qf[ks], bb[2], bb[3]);
            }
        }

        if (kt + 1 < nkt) load_kv(kt + 1);   // hide LDG under softmax+PV

        const float scale = 0.125f;
#pragma unroll
        for (int nt = 0; nt < 8; nt++)
#pragma unroll
            for (int r = 0; r < 4; r++) sf[nt][r] *= scale;

        if (k0 + 63 > q0 + wid * 16) {
#pragma unroll
            for (int nt = 0; nt < 8; nt++) {
                int c = k0 + nt * 8 + 2 * lm;
                if (c     > gr0)     sf[nt][0] = -1e30f;
                if (c + 1 > gr0)     sf[nt][1] = -1e30f;
                if (c     > gr0 + 8) sf[nt][2] = -1e30f;
                if (c + 1 > gr0 + 8) sf[nt][3] = -1e30f;
            }
        }

        // online softmax (rows gr0, gr0+8)
        float rm0 = -1e30f, rm1 = -1e30f;
#pragma unroll
        for (int nt = 0; nt < 8; nt++) {
            rm0 = fmaxf(rm0, fmaxf(sf[nt][0], sf[nt][1]));
            rm1 = fmaxf(rm1, fmaxf(sf[nt][2], sf[nt][3]));
        }
#pragma unroll
        for (int off = 1; off <= 2; off <<= 1) {
            rm0 = fmaxf(rm0, __shfl_xor_sync(0xffffffffu, rm0, off));
            rm1 = fmaxf(rm1, __shfl_xor_sync(0xffffffffu, rm1, off));
        }
        float nm0 = fmaxf(m0, rm0), nm1 = fmaxf(m1, rm1);
        float a0 = __expf(m0 - nm0), a1 = __expf(m1 - nm1);
        float rs0 = 0.0f, rs1 = 0.0f;
#pragma unroll
        for (int nt = 0; nt < 8; nt++) {
            sf[nt][0] = __expf(sf[nt][0] - nm0);
            sf[nt][1] = __expf(sf[nt][1] - nm0);
            sf[nt][2] = __expf(sf[nt][2] - nm1);
            sf[nt][3] = __expf(sf[nt][3] - nm1);
            rs0 += sf[nt][0] + sf[nt][1];
            rs1 += sf[nt][2] + sf[nt][3];
        }
#pragma unroll
        for (int off = 1; off <= 2; off <<= 1) {
            rs0 += __shfl_xor_sync(0xffffffffu, rs0, off);
            rs1 += __shfl_xor_sync(0xffffffffu, rs1, off);
        }
        l0 = l0 * a0 + rs0;  m0 = nm0;
        l1 = l1 * a1 + rs1;  m1 = nm1;
#pragma unroll
        for (int dt = 0; dt < 8; dt++) {
            oacc[dt][0] *= a0; oacc[dt][1] *= a0;
            oacc[dt][2] *= a1; oacc[dt][3] *= a1;
        }

        // P -> smem (tf32), warp-private rows
#pragma unroll
        for (int nt = 0; nt < 8; nt++) {
            int c = nt * 8 + 2 * lm;
            uint32_t p0 = f2tf32(sf[nt][0]), p1 = f2tf32(sf[nt][1]);
            uint32_t p2 = f2tf32(sf[nt][2]), p3 = f2tf32(sf[nt][3]);
            *(uint2*)&Ps[prow * FS + c]       = make_uint2(p0, p1);
            *(uint2*)&Ps[(prow + 8) * FS + c] = make_uint2(p2, p3);
        }
        __syncwarp();

        // O += P @ V
#pragma unroll
        for (int ks = 0; ks < 8; ks++) {
            const uint32_t kbB = ks * 32;
            uint32_t af[4];
            ldsm_x4(af, psb + pOff + kbB);
#pragma unroll
            for (int t = 0; t < 4; t++) {
                uint32_t bb[4];
                ldsm_x4(bb, vtBuf + kvOff[t] + kbB);
                mma_tf32(oacc[2 * t],     af, bb[0], bb[1]);
                mma_tf32(oacc[2 * t + 1], af, bb[2], bb[3]);
            }
        }

        if (kt + 1 < nkt) {
            store_kv(buf ^ 1);
            __syncthreads();   // single sync per tile
        }
    }

    float inv0 = 1.0f / l0, inv1 = 1.0f / l1;
#pragma unroll
    for (int dt = 0; dt < 8; dt++) {
        int d = dt * 8 + 2 * lm;
        float2 o0 = make_float2(oacc[dt][0] * inv0, oacc[dt][1] * inv0);
        float2 o1 = make_float2(oacc[dt][2] * inv1, oacc[dt][3] * inv1);
        *(float2*)(Og + base + (size_t)gr0 * DD + d) = o0;
        *(float2*)(Og + base + (size_t)(gr0 + 8) * DD + d) = o1;
    }
}

// ---------------------------------------------------------------------------
// Launch
// ---------------------------------------------------------------------------
extern "C" void kernel_launch(void* const* d_in, const int* in_sizes, int n_in,
                              void* d_out, int out_size)
{
    const float* query = (const float*)d_in[0];
    const float* key   = (const float*)d_in[1];
    const float* value = (const float*)d_in[2];
    const float* wq = (const float*)d_in[3];
    const float* bq = (const float*)d_in[4];
    const float* wk = (const float*)d_in[5];
    const float* bk = (const float*)d_in[6];
    const float* wv = (const float*)d_in[7];
    const float* bv = (const float*)d_in[8];
    const float* wo = (const float*)d_in[9];
    const float* bo = (const float*)d_in[10];
    float* out = (float*)d_out;

    float *q_s, *k_s, *v_s, *o_s;
    cudaGetSymbolAddress((void**)&q_s, g_q);
    cudaGetSymbolAddress((void**)&k_s, g_k);
    cudaGetSymbolAddress((void**)&v_s, g_v);
    cudaGetSymbolAddress((void**)&o_s, g_o);

    cudaFuncSetAttribute(flash_mma_kernel,
                         cudaFuncAttributeMaxDynamicSharedMemorySize, FLASH_SMEM);

    // 1. fused q/k/v projections
    dim3 gproj3(DD / 128, MROWS / 128, 3);
    gemm3_mma_kernel<<<gproj3, 128>>>(query, key, value, wq, wk, wv,
                                      bq, bk, bv, q_s, k_s, v_s);

    // 2. flash attention: 64 q-rows per CTA, 2 CTAs/SM
    dim3 gattn(SS / 64, HH, BB);   // (32, 16, 2) = 1024 CTAs
    flash_mma_kernel<<<gattn, 128, FLASH_SMEM>>>(q_s, k_s, v_s, o_s);

    // 3. output projection
    dim3 gproj1(DD / 128, MROWS / 128, 1);
    gemm3_mma_kernel<<<gproj1, 128>>>(o_s, o_s, o_s, wo, wo, wo,
                                      bo, bo, bo, out, out, out);
}